// round 1
// baseline (speedup 1.0000x reference)
#include <cuda_runtime.h>

// ---------------------------------------------------------------------------
// GlimpseNetwork: foveated patch extraction + 2 MLPs with training-mode BN.
// B=4096, H=W=128, C=1, G=14, K=4 patches (14,28,56,112 -> pooled to 14x14).
// phi: (4096, 784). what-MLP: 784->128 (BN,ReLU) ->256 (BN).
// where-MLP: 2->128 (BN,ReLU) ->256 (BN). out = relu(what + where): (4096,256).
// ---------------------------------------------------------------------------

#define BATCH 4096
#define HIMG  128
#define PHI_DIM 784
#define WIN   112
#define WSTRIDE 113   // odd stride: conflict-free column access

// Scratch (no cudaMalloc allowed)
__device__ float g_phi[BATCH * PHI_DIM];
__device__ float g_h1w[BATCH * 128];
__device__ float g_h1l[BATCH * 128];
__device__ float g_h2w[BATCH * 256];
__device__ float g_h2l[BATCH * 256];
__device__ float g_mean[1024];   // slots: [0]=w1(128) [256]=l1(128) [512]=w2(256) [768]=l2(256)
__device__ float g_rstd[1024];

// ---------------------------------------------------------------------------
// 1) Foveate: load the 112x112 window (all 4 patches are nested & concentric)
//    into SMEM once, then pool all 4 scales from SMEM.
// ---------------------------------------------------------------------------
__global__ void foveate_kernel(const float* __restrict__ x,
                               const float* __restrict__ loc,
                               float* __restrict__ phi)
{
    extern __shared__ float win[];   // WIN * WSTRIDE floats
    int b = blockIdx.x;
    float lx = loc[2 * b + 0];
    float ly = loc[2 * b + 1];
    // match jnp: (0.5*((loc+1)*H)).astype(int32)  (nonnegative -> trunc==floor)
    int cx = (int)(0.5f * ((lx + 1.0f) * 128.0f));
    int cy = (int)(0.5f * ((ly + 1.0f) * 128.0f));
    int row0 = cy - 56;
    int col0 = cx - 56;
    const float* img = x + (size_t)b * HIMG * HIMG;

    for (int idx = threadIdx.x; idx < WIN * WIN; idx += blockDim.x) {
        int wr = idx / WIN;
        int wc = idx - wr * WIN;
        int r = row0 + wr;
        int c = col0 + wc;
        float v = 0.0f;
        if ((unsigned)r < (unsigned)HIMG && (unsigned)c < (unsigned)HIMG)
            v = img[r * HIMG + c];
        win[wr * WSTRIDE + wc] = v;
    }
    __syncthreads();

    for (int o = threadIdx.x; o < PHI_DIM; o += blockDim.x) {
        int p = o / 196;            // patch index (0..3), pool factor k = 1<<p
        int rem = o - p * 196;
        int i = rem / 14;
        int j = rem - i * 14;
        int k = 1 << p;
        int start = 56 - 7 * k;     // window-local top-left of this patch
        int base = (start + i * k) * WSTRIDE + (start + j * k);
        float s = 0.0f;
        for (int di = 0; di < k; di++) {
            int rb = base + di * WSTRIDE;
            for (int dj = 0; dj < k; dj++)
                s += win[rb + dj];
        }
        phi[(size_t)b * PHI_DIM + o] = s * (1.0f / (float)(k * k));
    }
}

// ---------------------------------------------------------------------------
// 2) Tiled fp32 GEMM with bias: C = A(MxK) @ B(KxN) + bias.  BM=32 BN=128 BK=16
//    256 threads, each computes 4x4.  Requires M%32==0, N%128==0, K%16==0.
// ---------------------------------------------------------------------------
__global__ void gemm_bias(const float* __restrict__ A,
                          const float* __restrict__ Bm,
                          const float* __restrict__ bias,
                          float* __restrict__ C,
                          int M, int N, int K)
{
    __shared__ float As[16][36];    // [kk][row], padded; row*4 is 16B aligned (36*4=144)
    __shared__ float Bs[16][128];   // [kk][col]

    int tid = threadIdx.x;
    int m0 = blockIdx.y * 32;
    int n0 = blockIdx.x * 128;
    int trow = tid >> 5;   // 0..7
    int tcol = tid & 31;   // 0..31

    float acc[4][4] = {};

    for (int k0 = 0; k0 < K; k0 += 16) {
        // load A tile 32x16 (512 elems, 2 per thread)
        #pragma unroll
        for (int i = 0; i < 2; i++) {
            int idx = tid + i * 256;
            int r = idx >> 4;
            int kk = idx & 15;
            As[kk][r] = A[(size_t)(m0 + r) * K + k0 + kk];
        }
        // load B tile 16x128 (2048 elems, 8 per thread, fully coalesced)
        #pragma unroll
        for (int i = 0; i < 8; i++) {
            int idx = tid + i * 256;
            int kk = idx >> 7;
            int col = idx & 127;
            Bs[kk][col] = Bm[(size_t)(k0 + kk) * N + n0 + col];
        }
        __syncthreads();

        #pragma unroll
        for (int kk = 0; kk < 16; kk++) {
            float4 a4 = *(const float4*)&As[kk][trow * 4];
            float4 b4 = *(const float4*)&Bs[kk][tcol * 4];
            float av[4] = {a4.x, a4.y, a4.z, a4.w};
            float bv[4] = {b4.x, b4.y, b4.z, b4.w};
            #pragma unroll
            for (int i = 0; i < 4; i++)
                #pragma unroll
                for (int j = 0; j < 4; j++)
                    acc[i][j] += av[i] * bv[j];
        }
        __syncthreads();
    }

    #pragma unroll
    for (int i = 0; i < 4; i++) {
        int row = m0 + trow * 4 + i;
        #pragma unroll
        for (int j = 0; j < 4; j++) {
            int col = n0 + tcol * 4 + j;
            C[(size_t)row * N + col] = acc[i][j] + bias[col];
        }
    }
}

// ---------------------------------------------------------------------------
// 3) where first layer: (4096,2) @ (2,128) + bias  (trivial, elementwise)
// ---------------------------------------------------------------------------
__global__ void where1_kernel(const float* __restrict__ loc,
                              const float* __restrict__ W,
                              const float* __restrict__ bias,
                              float* __restrict__ out)
{
    int idx = blockIdx.x * blockDim.x + threadIdx.x;
    if (idx >= BATCH * 128) return;
    int b = idx >> 7;
    int c = idx & 127;
    out[idx] = loc[2 * b] * W[c] + loc[2 * b + 1] * W[128 + c] + bias[c];
}

// ---------------------------------------------------------------------------
// 4) Per-column batch stats (deterministic): one block per column.
// ---------------------------------------------------------------------------
__global__ void stats_kernel(const float* __restrict__ h, int NC,
                             float* __restrict__ mean, float* __restrict__ rstd)
{
    int c = blockIdx.x;
    float s = 0.0f, sq = 0.0f;
    for (int r = threadIdx.x; r < BATCH; r += 256) {
        float v = h[(size_t)r * NC + c];
        s += v;
        sq += v * v;
    }
    __shared__ float ss[256], sqq[256];
    ss[threadIdx.x] = s;
    sqq[threadIdx.x] = sq;
    __syncthreads();
    for (int off = 128; off > 0; off >>= 1) {
        if (threadIdx.x < off) {
            ss[threadIdx.x]  += ss[threadIdx.x + off];
            sqq[threadIdx.x] += sqq[threadIdx.x + off];
        }
        __syncthreads();
    }
    if (threadIdx.x == 0) {
        float m = ss[0] * (1.0f / (float)BATCH);
        float var = sqq[0] * (1.0f / (float)BATCH) - m * m;   // biased (ddof=0)
        mean[c] = m;
        rstd[c] = rsqrtf(var + 1e-5f);
    }
}

// ---------------------------------------------------------------------------
// 5) In-place BN + ReLU
// ---------------------------------------------------------------------------
__global__ void bnrelu_kernel(float* __restrict__ h, int NC,
                              const float* __restrict__ mean,
                              const float* __restrict__ rstd,
                              const float* __restrict__ gam,
                              const float* __restrict__ bet)
{
    int idx = blockIdx.x * blockDim.x + threadIdx.x;
    if (idx >= BATCH * NC) return;
    int c = idx & (NC - 1);   // NC is a power of two (128)
    float v = (h[idx] - mean[c]) * rstd[c] * gam[c] + bet[c];
    h[idx] = v > 0.0f ? v : 0.0f;
}

// ---------------------------------------------------------------------------
// 6) Final: relu( BN(h2_what) + BN(h2_where) )
// ---------------------------------------------------------------------------
__global__ void final_kernel(const float* __restrict__ h2w,
                             const float* __restrict__ h2l,
                             const float* __restrict__ mw, const float* __restrict__ rw,
                             const float* __restrict__ gw, const float* __restrict__ bw,
                             const float* __restrict__ ml, const float* __restrict__ rl,
                             const float* __restrict__ gl, const float* __restrict__ bl,
                             float* __restrict__ out)
{
    int idx = blockIdx.x * blockDim.x + threadIdx.x;
    if (idx >= BATCH * 256) return;
    int c = idx & 255;
    float vw = (h2w[idx] - mw[c]) * rw[c] * gw[c] + bw[c];
    float vl = (h2l[idx] - ml[c]) * rl[c] * gl[c] + bl[c];
    float v = vw + vl;
    out[idx] = v > 0.0f ? v : 0.0f;
}

// ---------------------------------------------------------------------------
extern "C" void kernel_launch(void* const* d_in, const int* in_sizes, int n_in,
                              void* d_out, int out_size)
{
    const float* x    = (const float*)d_in[0];
    const float* loc  = (const float*)d_in[1];
    const float* wW1  = (const float*)d_in[2];
    const float* wb1  = (const float*)d_in[3];
    const float* wg1  = (const float*)d_in[4];
    const float* wbe1 = (const float*)d_in[5];
    const float* wW2  = (const float*)d_in[6];
    const float* wb2  = (const float*)d_in[7];
    const float* wg2  = (const float*)d_in[8];
    const float* wbe2 = (const float*)d_in[9];
    const float* lW1  = (const float*)d_in[10];
    const float* lb1  = (const float*)d_in[11];
    const float* lg1  = (const float*)d_in[12];
    const float* lbe1 = (const float*)d_in[13];
    const float* lW2  = (const float*)d_in[14];
    const float* lb2  = (const float*)d_in[15];
    const float* lg2  = (const float*)d_in[16];
    const float* lbe2 = (const float*)d_in[17];
    float* out = (float*)d_out;

    float *phi, *h1w, *h1l, *h2w, *h2l, *mean, *rstd;
    cudaGetSymbolAddress((void**)&phi,  g_phi);
    cudaGetSymbolAddress((void**)&h1w,  g_h1w);
    cudaGetSymbolAddress((void**)&h1l,  g_h1l);
    cudaGetSymbolAddress((void**)&h2w,  g_h2w);
    cudaGetSymbolAddress((void**)&h2l,  g_h2l);
    cudaGetSymbolAddress((void**)&mean, g_mean);
    cudaGetSymbolAddress((void**)&rstd, g_rstd);

    const int fov_smem = WIN * WSTRIDE * sizeof(float);   // 50624 B > 48K
    cudaFuncSetAttribute(foveate_kernel,
                         cudaFuncAttributeMaxDynamicSharedMemorySize, fov_smem);

    // 1) foveate -> phi (4096, 784)
    foveate_kernel<<<BATCH, 256, fov_smem>>>(x, loc, phi);

    // 2) what layer1: phi @ W1 + b1 -> h1w (4096,128)
    {
        dim3 grid(128 / 128, BATCH / 32);
        gemm_bias<<<grid, 256>>>(phi, wW1, wb1, h1w, BATCH, 128, PHI_DIM);
    }
    // 3) where layer1
    where1_kernel<<<(BATCH * 128 + 255) / 256, 256>>>(loc, lW1, lb1, h1l);

    // 4) BN stats + apply + ReLU (layer 1)
    stats_kernel<<<128, 256>>>(h1w, 128, mean + 0,   rstd + 0);
    stats_kernel<<<128, 256>>>(h1l, 128, mean + 256, rstd + 256);
    bnrelu_kernel<<<(BATCH * 128 + 255) / 256, 256>>>(h1w, 128, mean + 0,   rstd + 0,   wg1, wbe1);
    bnrelu_kernel<<<(BATCH * 128 + 255) / 256, 256>>>(h1l, 128, mean + 256, rstd + 256, lg1, lbe1);

    // 5) layer2 GEMMs: (4096,128) @ (128,256) + bias
    {
        dim3 grid(256 / 128, BATCH / 32);
        gemm_bias<<<grid, 256>>>(h1w, wW2, wb2, h2w, BATCH, 256, 128);
        gemm_bias<<<grid, 256>>>(h1l, lW2, lb2, h2l, BATCH, 256, 128);
    }

    // 6) BN stats (layer 2) + final add + relu
    stats_kernel<<<256, 256>>>(h2w, 256, mean + 512, rstd + 512);
    stats_kernel<<<256, 256>>>(h2l, 256, mean + 768, rstd + 768);
    final_kernel<<<(BATCH * 256 + 255) / 256, 256>>>(
        h2w, h2l,
        mean + 512, rstd + 512, wg2, wbe2,
        mean + 768, rstd + 768, lg2, lbe2,
        out);
}

// round 2
// speedup vs baseline: 1.4575x; 1.4575x over previous
#include <cuda_runtime.h>

// ---------------------------------------------------------------------------
// GlimpseNetwork fused pipeline.
// B=4096, H=128, G=14, patches 14/28/56/112 -> pooled 14x14 each -> phi(4096,784)
// what: 784->128 (BN,ReLU) ->256 (BN) ; where: 2->128 (BN,ReLU) ->256 (BN)
// out = relu(what + where): (4096,256). Training-mode BN (batch stats, biased var).
// ---------------------------------------------------------------------------

#define BATCH 4096
#define HIMG  128
#define PHI_DIM 784

// Scratch (device globals; no cudaMalloc allowed)
__device__ float g_phi[BATCH * PHI_DIM];
__device__ float g_h1w[BATCH * 128];
__device__ float g_h1l[BATCH * 128];
__device__ float g_h2w[BATCH * 256];
__device__ float g_h2l[BATCH * 256];
// per-block column partials (deterministic: no atomics)
__device__ float g_p1w_s[128 * 128], g_p1w_q[128 * 128];
__device__ float g_p1l_s[32 * 128],  g_p1l_q[32 * 128];
__device__ float g_p2w_s[128 * 256], g_p2w_q[128 * 256];
__device__ float g_p2l_s[128 * 256], g_p2l_q[128 * 256];
// fused BN transforms: h_norm = fma(h, scale, shift)
__device__ float g_s1w[128], g_t1w[128], g_s1l[128], g_t1l[128];
__device__ float g_s2w[256], g_t2w[256], g_s2l[256], g_t2l[256];

// ---------------------------------------------------------------------------
// 1) Foveate via 2x2-pooled pyramid. All 4 patches are concentric + nested in
//    a 112x112 window. Pool 2x2 on load -> 56x56 SMEM (13KB) + raw 14x14 center.
//    scale0 = center; scale1 = pooled[21+i][21+j]; scale2 = 2x2 mean of pooled;
//    scale3 = 4x4 mean of pooled.  (exact up to fp rounding)
// ---------------------------------------------------------------------------
__global__ void foveate_kernel(const float* __restrict__ x,
                               const float* __restrict__ loc,
                               float* __restrict__ phi)
{
    __shared__ float pooled[56 * 57];   // odd stride
    __shared__ float center[196];
    int b = blockIdx.x;
    float lx = loc[2 * b + 0];
    float ly = loc[2 * b + 1];
    // match jnp: (0.5*((loc+1)*H)).astype(int32)
    int cx = (int)(0.5f * ((lx + 1.0f) * 128.0f));
    int cy = (int)(0.5f * ((ly + 1.0f) * 128.0f));
    int row0 = cy - 56;
    int col0 = cx - 56;
    const float* __restrict__ img = x + (size_t)b * HIMG * HIMG;

    for (int idx = threadIdx.x; idx < 56 * 56; idx += 256) {
        int pr = idx / 56;
        int pc = idx - pr * 56;
        int r = row0 + 2 * pr;
        int c = col0 + 2 * pc;
        float s = 0.0f;
        bool r0ok = (unsigned)r < 128u, r1ok = (unsigned)(r + 1) < 128u;
        bool c0ok = (unsigned)c < 128u, c1ok = (unsigned)(c + 1) < 128u;
        if (r0ok && c0ok) s += img[r * HIMG + c];
        if (r0ok && c1ok) s += img[r * HIMG + c + 1];
        if (r1ok && c0ok) s += img[(r + 1) * HIMG + c];
        if (r1ok && c1ok) s += img[(r + 1) * HIMG + c + 1];
        pooled[pr * 57 + pc] = s * 0.25f;
    }
    if (threadIdx.x < 196) {
        int i = threadIdx.x / 14;
        int j = threadIdx.x - i * 14;
        int r = row0 + 49 + i;
        int c = col0 + 49 + j;
        float v = 0.0f;
        if ((unsigned)r < 128u && (unsigned)c < 128u) v = img[r * HIMG + c];
        center[threadIdx.x] = v;
    }
    __syncthreads();

    float* __restrict__ ph = phi + (size_t)b * PHI_DIM;
    for (int o = threadIdx.x; o < PHI_DIM; o += 256) {
        int p = o / 196;
        int rem = o - p * 196;
        int i = rem / 14;
        int j = rem - i * 14;
        float v;
        if (p == 0) {
            v = center[rem];
        } else if (p == 1) {
            v = pooled[(21 + i) * 57 + 21 + j];
        } else if (p == 2) {
            int base = (14 + 2 * i) * 57 + 14 + 2 * j;
            v = (pooled[base] + pooled[base + 1] +
                 pooled[base + 57] + pooled[base + 58]) * 0.25f;
        } else {
            int base = (4 * i) * 57 + 4 * j;
            float s = 0.0f;
            #pragma unroll
            for (int di = 0; di < 4; di++)
                #pragma unroll
                for (int dj = 0; dj < 4; dj++)
                    s += pooled[base + di * 57 + dj];
            v = s * (1.0f / 16.0f);
        }
        ph[o] = v;
    }
}

// ---------------------------------------------------------------------------
// 2) Tiled fp32 GEMM + bias, fused column-stats epilogue.
//    BM=32 BN=128 BK=16, 256 threads, 4x4 per thread.
//    TA=true: apply relu(fma(a, sA[k], tA[k])) to A on load (BN+ReLU of prev layer).
//    Writes per-block column sum/sumsq partials to ps/pq (index by*N + col).
// ---------------------------------------------------------------------------
template <bool TA>
__global__ void gemm_kernel(const float* __restrict__ A,
                            const float* __restrict__ Bm,
                            const float* __restrict__ bias,
                            const float* __restrict__ sA,
                            const float* __restrict__ tA,
                            float* __restrict__ C,
                            float* __restrict__ ps,
                            float* __restrict__ pq,
                            int N, int K)
{
    __shared__ float As[16][36];
    __shared__ float Bs[16][128];
    __shared__ float rs[8][128];
    __shared__ float rq[8][128];

    int tid = threadIdx.x;
    int m0 = blockIdx.y * 32;
    int n0 = blockIdx.x * 128;
    int trow = tid >> 5;   // 0..7
    int tcol = tid & 31;   // 0..31

    float acc[4][4] = {};

    for (int k0 = 0; k0 < K; k0 += 16) {
        #pragma unroll
        for (int i = 0; i < 2; i++) {
            int idx = tid + i * 256;
            int r = idx >> 4;
            int kk = idx & 15;
            float v = A[(size_t)(m0 + r) * K + k0 + kk];
            if (TA) v = fmaxf(fmaf(v, sA[k0 + kk], tA[k0 + kk]), 0.0f);
            As[kk][r] = v;
        }
        #pragma unroll
        for (int i = 0; i < 8; i++) {
            int idx = tid + i * 256;
            int kk = idx >> 7;
            int col = idx & 127;
            Bs[kk][col] = Bm[(size_t)(k0 + kk) * N + n0 + col];
        }
        __syncthreads();

        #pragma unroll
        for (int kk = 0; kk < 16; kk++) {
            float4 a4 = *(const float4*)&As[kk][trow * 4];
            float4 b4 = *(const float4*)&Bs[kk][tcol * 4];
            float av[4] = {a4.x, a4.y, a4.z, a4.w};
            float bv[4] = {b4.x, b4.y, b4.z, b4.w};
            #pragma unroll
            for (int i = 0; i < 4; i++)
                #pragma unroll
                for (int j = 0; j < 4; j++)
                    acc[i][j] += av[i] * bv[j];
        }
        __syncthreads();
    }

    // epilogue: store C (+bias) and accumulate per-column stats
    float colS[4] = {}, colQ[4] = {};
    #pragma unroll
    for (int i = 0; i < 4; i++) {
        int row = m0 + trow * 4 + i;
        #pragma unroll
        for (int j = 0; j < 4; j++) {
            int col = n0 + tcol * 4 + j;
            float v = acc[i][j] + bias[col];
            C[(size_t)row * N + col] = v;
            colS[j] += v;
            colQ[j] += v * v;
        }
    }
    #pragma unroll
    for (int j = 0; j < 4; j++) {
        rs[trow][tcol * 4 + j] = colS[j];
        rq[trow][tcol * 4 + j] = colQ[j];
    }
    __syncthreads();
    if (tid < 128) {
        float s = 0.0f, q = 0.0f;
        #pragma unroll
        for (int r = 0; r < 8; r++) { s += rs[r][tid]; q += rq[r][tid]; }
        ps[blockIdx.y * N + n0 + tid] = s;
        pq[blockIdx.y * N + n0 + tid] = q;
    }
}

// ---------------------------------------------------------------------------
// 3) where layer1 (4096,2)@(2,128)+bias with fused stats partials.
//    32 blocks x 256 threads; block handles 128 rows; thread owns one column.
// ---------------------------------------------------------------------------
__global__ void where1_kernel(const float* __restrict__ loc,
                              const float* __restrict__ W,
                              const float* __restrict__ bias)
{
    int c = threadIdx.x & 127;
    int half = threadIdx.x >> 7;
    int r0 = blockIdx.x * 128 + half * 64;
    float w0 = W[c], w1 = W[128 + c], bb = bias[c];
    float s = 0.0f, q = 0.0f;
    for (int r = r0; r < r0 + 64; r++) {
        float2 l = ((const float2*)loc)[r];
        float v = fmaf(l.x, w0, fmaf(l.y, w1, bb));
        g_h1l[(size_t)r * 128 + c] = v;
        s += v;
        q += v * v;
    }
    __shared__ float rs[256], rq[256];
    rs[threadIdx.x] = s;
    rq[threadIdx.x] = q;
    __syncthreads();
    if (threadIdx.x < 128) {
        g_p1l_s[blockIdx.x * 128 + threadIdx.x] = rs[threadIdx.x] + rs[threadIdx.x + 128];
        g_p1l_q[blockIdx.x * 128 + threadIdx.x] = rq[threadIdx.x] + rq[threadIdx.x + 128];
    }
}

// ---------------------------------------------------------------------------
// 4) Finalize layer-1 stats -> fused BN scale/shift. 1 block, 256 threads.
// ---------------------------------------------------------------------------
__global__ void finalize1_kernel(const float* __restrict__ g1w, const float* __restrict__ be1w,
                                 const float* __restrict__ g1l, const float* __restrict__ be1l)
{
    int t = threadIdx.x;
    if (t < 128) {
        float s = 0.0f, q = 0.0f;
        for (int k = 0; k < 128; k++) { s += g_p1w_s[k * 128 + t]; q += g_p1w_q[k * 128 + t]; }
        float m = s * (1.0f / BATCH);
        float var = q * (1.0f / BATCH) - m * m;
        float r = rsqrtf(var + 1e-5f);
        float sc = r * g1w[t];
        g_s1w[t] = sc;
        g_t1w[t] = be1w[t] - m * sc;
    } else {
        int c = t - 128;
        float s = 0.0f, q = 0.0f;
        for (int k = 0; k < 32; k++) { s += g_p1l_s[k * 128 + c]; q += g_p1l_q[k * 128 + c]; }
        float m = s * (1.0f / BATCH);
        float var = q * (1.0f / BATCH) - m * m;
        float r = rsqrtf(var + 1e-5f);
        float sc = r * g1l[c];
        g_s1l[c] = sc;
        g_t1l[c] = be1l[c] - m * sc;
    }
}

// ---------------------------------------------------------------------------
// 5) Finalize layer-2 stats. 1 block, 256 threads (each does both branches).
// ---------------------------------------------------------------------------
__global__ void finalize2_kernel(const float* __restrict__ g2w, const float* __restrict__ be2w,
                                 const float* __restrict__ g2l, const float* __restrict__ be2l)
{
    int t = threadIdx.x;   // column 0..255
    float sw = 0.0f, qw = 0.0f, sl = 0.0f, ql = 0.0f;
    for (int k = 0; k < 128; k++) {
        sw += g_p2w_s[k * 256 + t];
        qw += g_p2w_q[k * 256 + t];
        sl += g_p2l_s[k * 256 + t];
        ql += g_p2l_q[k * 256 + t];
    }
    float mw = sw * (1.0f / BATCH);
    float vw = qw * (1.0f / BATCH) - mw * mw;
    float rw = rsqrtf(vw + 1e-5f);
    float scw = rw * g2w[t];
    g_s2w[t] = scw;
    g_t2w[t] = be2w[t] - mw * scw;

    float ml = sl * (1.0f / BATCH);
    float vl = ql * (1.0f / BATCH) - ml * ml;
    float rl = rsqrtf(vl + 1e-5f);
    float scl = rl * g2l[t];
    g_s2l[t] = scl;
    g_t2l[t] = be2l[t] - ml * scl;
}

// ---------------------------------------------------------------------------
// 6) Final: out = relu( BN(h2w) + BN(h2l) )
// ---------------------------------------------------------------------------
__global__ void final_kernel(float* __restrict__ out)
{
    int idx = blockIdx.x * 256 + threadIdx.x;
    int c = idx & 255;
    float vw = fmaf(g_h2w[idx], g_s2w[c], g_t2w[c]);
    float vl = fmaf(g_h2l[idx], g_s2l[c], g_t2l[c]);
    float v = vw + vl;
    out[idx] = v > 0.0f ? v : 0.0f;
}

// ---------------------------------------------------------------------------
extern "C" void kernel_launch(void* const* d_in, const int* in_sizes, int n_in,
                              void* d_out, int out_size)
{
    const float* x    = (const float*)d_in[0];
    const float* loc  = (const float*)d_in[1];
    const float* wW1  = (const float*)d_in[2];
    const float* wb1  = (const float*)d_in[3];
    const float* wg1  = (const float*)d_in[4];
    const float* wbe1 = (const float*)d_in[5];
    const float* wW2  = (const float*)d_in[6];
    const float* wb2  = (const float*)d_in[7];
    const float* wg2  = (const float*)d_in[8];
    const float* wbe2 = (const float*)d_in[9];
    const float* lW1  = (const float*)d_in[10];
    const float* lb1  = (const float*)d_in[11];
    const float* lg1  = (const float*)d_in[12];
    const float* lbe1 = (const float*)d_in[13];
    const float* lW2  = (const float*)d_in[14];
    const float* lb2  = (const float*)d_in[15];
    const float* lg2  = (const float*)d_in[16];
    const float* lbe2 = (const float*)d_in[17];
    float* out = (float*)d_out;

    float *phi, *h1w, *h1l, *h2w, *h2l;
    float *p1w_s, *p1w_q, *p2w_s, *p2w_q, *p2l_s, *p2l_q;
    float *s1w, *t1w, *s1l, *t1l;
    cudaGetSymbolAddress((void**)&phi, g_phi);
    cudaGetSymbolAddress((void**)&h1w, g_h1w);
    cudaGetSymbolAddress((void**)&h1l, g_h1l);
    cudaGetSymbolAddress((void**)&h2w, g_h2w);
    cudaGetSymbolAddress((void**)&h2l, g_h2l);
    cudaGetSymbolAddress((void**)&p1w_s, g_p1w_s);
    cudaGetSymbolAddress((void**)&p1w_q, g_p1w_q);
    cudaGetSymbolAddress((void**)&p2w_s, g_p2w_s);
    cudaGetSymbolAddress((void**)&p2w_q, g_p2w_q);
    cudaGetSymbolAddress((void**)&p2l_s, g_p2l_s);
    cudaGetSymbolAddress((void**)&p2l_q, g_p2l_q);
    cudaGetSymbolAddress((void**)&s1w, g_s1w);
    cudaGetSymbolAddress((void**)&t1w, g_t1w);
    cudaGetSymbolAddress((void**)&s1l, g_s1l);
    cudaGetSymbolAddress((void**)&t1l, g_t1l);

    // 1) foveate -> phi (4096, 784)
    foveate_kernel<<<BATCH, 256>>>(x, loc, phi);

    // 2) what layer1: phi @ W1 + b1 -> h1w, with fused stats partials
    {
        dim3 grid(1, BATCH / 32);
        gemm_kernel<false><<<grid, 256>>>(phi, wW1, wb1, nullptr, nullptr,
                                          h1w, p1w_s, p1w_q, 128, PHI_DIM);
    }
    // 3) where layer1 + stats partials
    where1_kernel<<<32, 256>>>(loc, lW1, lb1);

    // 4) finalize layer-1 BN params
    finalize1_kernel<<<1, 256>>>(wg1, wbe1, lg1, lbe1);

    // 5) layer2 GEMMs with fused BN+ReLU on A and fused stats partials
    {
        dim3 grid(2, BATCH / 32);
        gemm_kernel<true><<<grid, 256>>>(h1w, wW2, wb2, s1w, t1w,
                                         h2w, p2w_s, p2w_q, 256, 128);
        gemm_kernel<true><<<grid, 256>>>(h1l, lW2, lb2, s1l, t1l,
                                         h2l, p2l_s, p2l_q, 256, 128);
    }

    // 6) finalize layer-2 BN params
    finalize2_kernel<<<1, 256>>>(wg2, wbe2, lg2, lbe2);

    // 7) final add + relu
    final_kernel<<<BATCH * 256 / 256, 256>>>(out);
}

// round 3
// speedup vs baseline: 1.6712x; 1.1466x over previous
#include <cuda_runtime.h>

// ---------------------------------------------------------------------------
// GlimpseNetwork fused pipeline.  B=4096, H=128, G=14, patches 14/28/56/112.
// ---------------------------------------------------------------------------

#define BATCH 4096
#define HIMG  128
#define PHI_DIM 784

typedef unsigned long long u64;

__device__ __forceinline__ u64 pk2(float x, float y) {
    u64 r; asm("mov.b64 %0, {%1, %2};" : "=l"(r) : "f"(x), "f"(y)); return r;
}
__device__ __forceinline__ void fma2(u64& d, u64 a, u64 b) {
    asm("fma.rn.f32x2 %0, %1, %2, %0;" : "+l"(d) : "l"(a), "l"(b));
}
__device__ __forceinline__ float2 upk(u64 v) {
    float2 f; asm("mov.b64 {%0, %1}, %2;" : "=f"(f.x), "=f"(f.y) : "l"(v)); return f;
}

// Scratch (device globals; no cudaMalloc allowed)
__device__ float g_phi[BATCH * PHI_DIM];
__device__ float g_h1w[BATCH * 128];
__device__ float g_h1l[BATCH * 128];
__device__ float g_h2w[BATCH * 256];
__device__ float g_h2l[BATCH * 256];
// per-block column partials (deterministic: no atomics)
__device__ float g_p1w_s[128 * 128], g_p1w_q[128 * 128];
__device__ float g_p1l_s[32 * 128],  g_p1l_q[32 * 128];
__device__ float g_p2w_s[128 * 256], g_p2w_q[128 * 256];
__device__ float g_p2l_s[128 * 256], g_p2l_q[128 * 256];
// fused BN transforms: h_norm = fma(h, scale, shift)
__device__ float g_s1w[128], g_t1w[128], g_s1l[128], g_t1l[128];
__device__ float g_s2w[256], g_t2w[256], g_s2l[256], g_t2l[256];

// ---------------------------------------------------------------------------
// 1) Foveate via 2x2-pooled pyramid (patches are concentric & nested in 112x112).
// ---------------------------------------------------------------------------
__global__ void foveate_kernel(const float* __restrict__ x,
                               const float* __restrict__ loc,
                               float* __restrict__ phi)
{
    __shared__ float pooled[56 * 57];
    __shared__ float center[196];
    int b = blockIdx.x;
    float lx = loc[2 * b + 0];
    float ly = loc[2 * b + 1];
    int cx = (int)(0.5f * ((lx + 1.0f) * 128.0f));
    int cy = (int)(0.5f * ((ly + 1.0f) * 128.0f));
    int row0 = cy - 56;
    int col0 = cx - 56;
    const float* __restrict__ img = x + (size_t)b * HIMG * HIMG;

    for (int idx = threadIdx.x; idx < 56 * 56; idx += 256) {
        int pr = idx / 56;
        int pc = idx - pr * 56;
        int r = row0 + 2 * pr;
        int c = col0 + 2 * pc;
        float s = 0.0f;
        bool r0ok = (unsigned)r < 128u, r1ok = (unsigned)(r + 1) < 128u;
        bool c0ok = (unsigned)c < 128u, c1ok = (unsigned)(c + 1) < 128u;
        if (r0ok && c0ok) s += img[r * HIMG + c];
        if (r0ok && c1ok) s += img[r * HIMG + c + 1];
        if (r1ok && c0ok) s += img[(r + 1) * HIMG + c];
        if (r1ok && c1ok) s += img[(r + 1) * HIMG + c + 1];
        pooled[pr * 57 + pc] = s * 0.25f;
    }
    if (threadIdx.x < 196) {
        int i = threadIdx.x / 14;
        int j = threadIdx.x - i * 14;
        int r = row0 + 49 + i;
        int c = col0 + 49 + j;
        float v = 0.0f;
        if ((unsigned)r < 128u && (unsigned)c < 128u) v = img[r * HIMG + c];
        center[threadIdx.x] = v;
    }
    __syncthreads();

    float* __restrict__ ph = phi + (size_t)b * PHI_DIM;
    for (int o = threadIdx.x; o < PHI_DIM; o += 256) {
        int p = o / 196;
        int rem = o - p * 196;
        int i = rem / 14;
        int j = rem - i * 14;
        float v;
        if (p == 0) {
            v = center[rem];
        } else if (p == 1) {
            v = pooled[(21 + i) * 57 + 21 + j];
        } else if (p == 2) {
            int base = (14 + 2 * i) * 57 + 14 + 2 * j;
            v = (pooled[base] + pooled[base + 1] +
                 pooled[base + 57] + pooled[base + 58]) * 0.25f;
        } else {
            int base = (4 * i) * 57 + 4 * j;
            float s = 0.0f;
            #pragma unroll
            for (int di = 0; di < 4; di++)
                #pragma unroll
                for (int dj = 0; dj < 4; dj++)
                    s += pooled[base + di * 57 + dj];
            v = s * (1.0f / 16.0f);
        }
        ph[o] = v;
    }
}

// ---------------------------------------------------------------------------
// 2) GEMM body (device function): BM=32 BN=128 BK=16, 256 thr, 4x4/thread,
//    packed-f32x2 FMA inner loop, fused bias + column-stats epilogue.
//    TA: apply relu(fma(a, sA[k], tA[k])) on A load.
// ---------------------------------------------------------------------------
template <bool TA>
__device__ __forceinline__ void gemm_body(const float* __restrict__ A,
                                          const float* __restrict__ Bm,
                                          const float* __restrict__ bias,
                                          const float* __restrict__ sA,
                                          const float* __restrict__ tA,
                                          float* __restrict__ C,
                                          float* __restrict__ ps,
                                          float* __restrict__ pq,
                                          int N, int K, int mb, int nb)
{
    __shared__ float As[16][36];
    __shared__ float Bs[16][128];
    __shared__ float rs[8][128];
    __shared__ float rq[8][128];

    int tid = threadIdx.x;
    int m0 = mb * 32;
    int n0 = nb * 128;
    int trow = tid >> 5;
    int tcol = tid & 31;

    u64 acc[4][2];
    #pragma unroll
    for (int i = 0; i < 4; i++) { acc[i][0] = 0ull; acc[i][1] = 0ull; }

    for (int k0 = 0; k0 < K; k0 += 16) {
        #pragma unroll
        for (int i = 0; i < 2; i++) {
            int idx = tid + i * 256;
            int r = idx >> 4;
            int kk = idx & 15;
            float v = A[(size_t)(m0 + r) * K + k0 + kk];
            if (TA) v = fmaxf(fmaf(v, sA[k0 + kk], tA[k0 + kk]), 0.0f);
            As[kk][r] = v;
        }
        #pragma unroll
        for (int i = 0; i < 8; i++) {
            int idx = tid + i * 256;
            int kk = idx >> 7;
            int col = idx & 127;
            Bs[kk][col] = Bm[(size_t)(k0 + kk) * N + n0 + col];
        }
        __syncthreads();

        #pragma unroll
        for (int kk = 0; kk < 16; kk++) {
            float4 a4 = *(const float4*)&As[kk][trow * 4];   // warp-uniform broadcast
            float4 b4 = *(const float4*)&Bs[kk][tcol * 4];
            u64 b01 = pk2(b4.x, b4.y);
            u64 b23 = pk2(b4.z, b4.w);
            u64 ad;
            ad = pk2(a4.x, a4.x); fma2(acc[0][0], ad, b01); fma2(acc[0][1], ad, b23);
            ad = pk2(a4.y, a4.y); fma2(acc[1][0], ad, b01); fma2(acc[1][1], ad, b23);
            ad = pk2(a4.z, a4.z); fma2(acc[2][0], ad, b01); fma2(acc[2][1], ad, b23);
            ad = pk2(a4.w, a4.w); fma2(acc[3][0], ad, b01); fma2(acc[3][1], ad, b23);
        }
        __syncthreads();
    }

    // epilogue: C = acc + bias, accumulate per-column sum/sumsq
    float colS[4] = {}, colQ[4] = {};
    #pragma unroll
    for (int i = 0; i < 4; i++) {
        int row = m0 + trow * 4 + i;
        float2 v01 = upk(acc[i][0]);
        float2 v23 = upk(acc[i][1]);
        float v[4] = {v01.x, v01.y, v23.x, v23.y};
        #pragma unroll
        for (int j = 0; j < 4; j++) {
            int col = n0 + tcol * 4 + j;
            float o = v[j] + bias[col];
            C[(size_t)row * N + col] = o;
            colS[j] += o;
            colQ[j] += o * o;
        }
    }
    #pragma unroll
    for (int j = 0; j < 4; j++) {
        rs[trow][tcol * 4 + j] = colS[j];
        rq[trow][tcol * 4 + j] = colQ[j];
    }
    __syncthreads();
    if (tid < 128) {
        float s = 0.0f, q = 0.0f;
        #pragma unroll
        for (int r = 0; r < 8; r++) { s += rs[r][tid]; q += rq[r][tid]; }
        ps[mb * N + n0 + tid] = s;
        pq[mb * N + n0 + tid] = q;
    }
}

// layer-1 what GEMM: phi(4096,784) @ W1(784,128)
__global__ void gemm1_kernel(const float* __restrict__ W1,
                             const float* __restrict__ b1)
{
    gemm_body<false>(g_phi, W1, b1, nullptr, nullptr,
                     g_h1w, g_p1w_s, g_p1w_q, 128, PHI_DIM,
                     blockIdx.y, 0);
}

// layer-2 GEMMs merged: z=0 what, z=1 where. A gets fused BN+ReLU.
__global__ void gemm2_kernel(const float* __restrict__ wW2, const float* __restrict__ wb2,
                             const float* __restrict__ lW2, const float* __restrict__ lb2)
{
    if (blockIdx.z == 0)
        gemm_body<true>(g_h1w, wW2, wb2, g_s1w, g_t1w,
                        g_h2w, g_p2w_s, g_p2w_q, 256, 128,
                        blockIdx.y, blockIdx.x);
    else
        gemm_body<true>(g_h1l, lW2, lb2, g_s1l, g_t1l,
                        g_h2l, g_p2l_s, g_p2l_q, 256, 128,
                        blockIdx.y, blockIdx.x);
}

// ---------------------------------------------------------------------------
// 3) where layer1: (4096,2)@(2,128)+bias with fused stats partials.
// ---------------------------------------------------------------------------
__global__ void where1_kernel(const float* __restrict__ loc,
                              const float* __restrict__ W,
                              const float* __restrict__ bias)
{
    int c = threadIdx.x & 127;
    int half = threadIdx.x >> 7;
    int r0 = blockIdx.x * 128 + half * 64;
    float w0 = W[c], w1 = W[128 + c], bb = bias[c];
    float s = 0.0f, q = 0.0f;
    for (int r = r0; r < r0 + 64; r++) {
        float2 l = ((const float2*)loc)[r];
        float v = fmaf(l.x, w0, fmaf(l.y, w1, bb));
        g_h1l[(size_t)r * 128 + c] = v;
        s += v;
        q += v * v;
    }
    __shared__ float rs[256], rq[256];
    rs[threadIdx.x] = s;
    rq[threadIdx.x] = q;
    __syncthreads();
    if (threadIdx.x < 128) {
        g_p1l_s[blockIdx.x * 128 + threadIdx.x] = rs[threadIdx.x] + rs[threadIdx.x + 128];
        g_p1l_q[blockIdx.x * 128 + threadIdx.x] = rq[threadIdx.x] + rq[threadIdx.x + 128];
    }
}

// ---------------------------------------------------------------------------
// 4) Parallel finalize: one block PER COLUMN, one thread per partial.
//    Layer 1: 256 blocks (0..127 what col, 128..255 where col), 128 threads.
// ---------------------------------------------------------------------------
__device__ __forceinline__ void reduce_finalize(float s, float q, int c,
                                                const float* __restrict__ gam,
                                                const float* __restrict__ bet,
                                                float* __restrict__ sc_out,
                                                float* __restrict__ sh_out)
{
    __shared__ float rs[128], rq[128];
    rs[threadIdx.x] = s;
    rq[threadIdx.x] = q;
    __syncthreads();
    #pragma unroll
    for (int off = 64; off >= 32; off >>= 1) {
        if (threadIdx.x < off) {
            rs[threadIdx.x] += rs[threadIdx.x + off];
            rq[threadIdx.x] += rq[threadIdx.x + off];
        }
        __syncthreads();
    }
    if (threadIdx.x < 32) {
        float ss = rs[threadIdx.x];
        float qq = rq[threadIdx.x];
        #pragma unroll
        for (int off = 16; off > 0; off >>= 1) {
            ss += __shfl_down_sync(0xffffffffu, ss, off);
            qq += __shfl_down_sync(0xffffffffu, qq, off);
        }
        if (threadIdx.x == 0) {
            float m = ss * (1.0f / BATCH);
            float var = qq * (1.0f / BATCH) - m * m;
            float r = rsqrtf(var + 1e-5f);
            float sc = r * gam[c];
            sc_out[c] = sc;
            sh_out[c] = bet[c] - m * sc;
        }
    }
}

__global__ void finalize1_kernel(const float* __restrict__ g1w, const float* __restrict__ be1w,
                                 const float* __restrict__ g1l, const float* __restrict__ be1l)
{
    int t = threadIdx.x;
    if (blockIdx.x < 128) {
        int c = blockIdx.x;
        reduce_finalize(g_p1w_s[t * 128 + c], g_p1w_q[t * 128 + c],
                        c, g1w, be1w, g_s1w, g_t1w);
    } else {
        int c = blockIdx.x - 128;
        float s = (t < 32) ? g_p1l_s[t * 128 + c] : 0.0f;
        float q = (t < 32) ? g_p1l_q[t * 128 + c] : 0.0f;
        reduce_finalize(s, q, c, g1l, be1l, g_s1l, g_t1l);
    }
}

// Layer 2: 512 blocks (0..255 what col, 256..511 where col), 128 threads.
__global__ void finalize2_kernel(const float* __restrict__ g2w, const float* __restrict__ be2w,
                                 const float* __restrict__ g2l, const float* __restrict__ be2l)
{
    int t = threadIdx.x;
    if (blockIdx.x < 256) {
        int c = blockIdx.x;
        reduce_finalize(g_p2w_s[t * 256 + c], g_p2w_q[t * 256 + c],
                        c, g2w, be2w, g_s2w, g_t2w);
    } else {
        int c = blockIdx.x - 256;
        reduce_finalize(g_p2l_s[t * 256 + c], g_p2l_q[t * 256 + c],
                        c, g2l, be2l, g_s2l, g_t2l);
    }
}

// ---------------------------------------------------------------------------
// 5) Final: out = relu( BN(h2w) + BN(h2l) )
// ---------------------------------------------------------------------------
__global__ void final_kernel(float* __restrict__ out)
{
    int idx = blockIdx.x * 256 + threadIdx.x;
    int c = idx & 255;
    float vw = fmaf(g_h2w[idx], g_s2w[c], g_t2w[c]);
    float vl = fmaf(g_h2l[idx], g_s2l[c], g_t2l[c]);
    float v = vw + vl;
    out[idx] = v > 0.0f ? v : 0.0f;
}

// ---------------------------------------------------------------------------
extern "C" void kernel_launch(void* const* d_in, const int* in_sizes, int n_in,
                              void* d_out, int out_size)
{
    const float* x    = (const float*)d_in[0];
    const float* loc  = (const float*)d_in[1];
    const float* wW1  = (const float*)d_in[2];
    const float* wb1  = (const float*)d_in[3];
    const float* wg1  = (const float*)d_in[4];
    const float* wbe1 = (const float*)d_in[5];
    const float* wW2  = (const float*)d_in[6];
    const float* wb2  = (const float*)d_in[7];
    const float* wg2  = (const float*)d_in[8];
    const float* wbe2 = (const float*)d_in[9];
    const float* lW1  = (const float*)d_in[10];
    const float* lb1  = (const float*)d_in[11];
    const float* lg1  = (const float*)d_in[12];
    const float* lbe1 = (const float*)d_in[13];
    const float* lW2  = (const float*)d_in[14];
    const float* lb2  = (const float*)d_in[15];
    const float* lg2  = (const float*)d_in[16];
    const float* lbe2 = (const float*)d_in[17];
    float* out = (float*)d_out;

    float* phi;
    cudaGetSymbolAddress((void**)&phi, g_phi);

    // 1) foveate -> phi (4096, 784)
    foveate_kernel<<<BATCH, 256>>>(x, loc, phi);

    // 2) what layer1 (fused stats partials)
    {
        dim3 grid(1, BATCH / 32);
        gemm1_kernel<<<grid, 256>>>(wW1, wb1);
    }
    // 3) where layer1 (fused stats partials)
    where1_kernel<<<32, 256>>>(loc, lW1, lb1);

    // 4) finalize layer-1 BN params (parallel)
    finalize1_kernel<<<256, 128>>>(wg1, wbe1, lg1, lbe1);

    // 5) both layer-2 GEMMs in one launch (fused BN+ReLU on A, stats partials)
    {
        dim3 grid(2, BATCH / 32, 2);
        gemm2_kernel<<<grid, 256>>>(wW2, wb2, lW2, lb2);
    }

    // 6) finalize layer-2 BN params (parallel)
    finalize2_kernel<<<512, 128>>>(wg2, wbe2, lg2, lbe2);

    // 7) final add + relu
    final_kernel<<<BATCH * 256 / 256, 256>>>(out);
}

// round 4
// speedup vs baseline: 1.8748x; 1.1218x over previous
#include <cuda_runtime.h>

// ---------------------------------------------------------------------------
// GlimpseNetwork fused pipeline.  B=4096, H=128, G=14, patches 14/28/56/112.
// TF32 tensor-core GEMMs, fused BN stats, 6 launches.
// ---------------------------------------------------------------------------

#define BATCH 4096
#define HIMG  128
#define PHI_DIM 784

// Scratch (device globals; no cudaMalloc allowed)
__device__ float g_phi[BATCH * PHI_DIM];
__device__ float g_h1w[BATCH * 128];
__device__ float g_h1l[BATCH * 128];
__device__ float g_h2w[BATCH * 256];
__device__ float g_h2l[BATCH * 256];
// per-block column partials (deterministic: no atomics)
__device__ float g_p1w_s[128 * 128], g_p1w_q[128 * 128];
__device__ float g_p1l_s[32 * 128],  g_p1l_q[32 * 128];
__device__ float g_p2w_s[128 * 256], g_p2w_q[128 * 256];
__device__ float g_p2l_s[128 * 256], g_p2l_q[128 * 256];
// fused BN transforms: h_norm = fma(h, scale, shift)
__device__ float g_s1w[128], g_t1w[128], g_s1l[128], g_t1l[128];
__device__ float g_s2w[256], g_t2w[256], g_s2l[256], g_t2l[256];

__device__ __forceinline__ unsigned f2tf(float v) {
    unsigned r;
    asm("cvt.rna.tf32.f32 %0, %1;" : "=r"(r) : "f"(v));
    return r;
}

__device__ __forceinline__ void mma_tf32(float* d, const unsigned* a, const unsigned* b) {
    asm volatile(
        "mma.sync.aligned.m16n8k8.row.col.f32.tf32.tf32.f32 "
        "{%0,%1,%2,%3}, {%4,%5,%6,%7}, {%8,%9}, {%0,%1,%2,%3};"
        : "+f"(d[0]), "+f"(d[1]), "+f"(d[2]), "+f"(d[3])
        : "r"(a[0]), "r"(a[1]), "r"(a[2]), "r"(a[3]), "r"(b[0]), "r"(b[1]));
}

// ---------------------------------------------------------------------------
// 1) Foveate (2x2-pooled pyramid) + folded where-layer1 (blocks 0..31).
// ---------------------------------------------------------------------------
__global__ void foveate_kernel(const float* __restrict__ x,
                               const float* __restrict__ loc,
                               float* __restrict__ phi,
                               const float* __restrict__ lW1,
                               const float* __restrict__ lb1)
{
    __shared__ float pooled[56 * 57];
    __shared__ float center[196];
    __shared__ float wrs[256], wrq[256];
    int b = blockIdx.x;
    float lx = loc[2 * b + 0];
    float ly = loc[2 * b + 1];
    int cx = (int)(0.5f * ((lx + 1.0f) * 128.0f));
    int cy = (int)(0.5f * ((ly + 1.0f) * 128.0f));
    int row0 = cy - 56;
    int col0 = cx - 56;
    const float* __restrict__ img = x + (size_t)b * HIMG * HIMG;

    for (int idx = threadIdx.x; idx < 56 * 56; idx += 256) {
        int pr = idx / 56;
        int pc = idx - pr * 56;
        int r = row0 + 2 * pr;
        int c = col0 + 2 * pc;
        float s = 0.0f;
        bool r0ok = (unsigned)r < 128u, r1ok = (unsigned)(r + 1) < 128u;
        bool c0ok = (unsigned)c < 128u, c1ok = (unsigned)(c + 1) < 128u;
        if (r0ok && c0ok) s += img[r * HIMG + c];
        if (r0ok && c1ok) s += img[r * HIMG + c + 1];
        if (r1ok && c0ok) s += img[(r + 1) * HIMG + c];
        if (r1ok && c1ok) s += img[(r + 1) * HIMG + c + 1];
        pooled[pr * 57 + pc] = s * 0.25f;
    }
    if (threadIdx.x < 196) {
        int i = threadIdx.x / 14;
        int j = threadIdx.x - i * 14;
        int r = row0 + 49 + i;
        int c = col0 + 49 + j;
        float v = 0.0f;
        if ((unsigned)r < 128u && (unsigned)c < 128u) v = img[r * HIMG + c];
        center[threadIdx.x] = v;
    }
    __syncthreads();

    float* __restrict__ ph = phi + (size_t)b * PHI_DIM;
    for (int o = threadIdx.x; o < PHI_DIM; o += 256) {
        int p = o / 196;
        int rem = o - p * 196;
        int i = rem / 14;
        int j = rem - i * 14;
        float v;
        if (p == 0) {
            v = center[rem];
        } else if (p == 1) {
            v = pooled[(21 + i) * 57 + 21 + j];
        } else if (p == 2) {
            int base = (14 + 2 * i) * 57 + 14 + 2 * j;
            v = (pooled[base] + pooled[base + 1] +
                 pooled[base + 57] + pooled[base + 58]) * 0.25f;
        } else {
            int base = (4 * i) * 57 + 4 * j;
            float s = 0.0f;
            #pragma unroll
            for (int di = 0; di < 4; di++)
                #pragma unroll
                for (int dj = 0; dj < 4; dj++)
                    s += pooled[base + di * 57 + dj];
            v = s * (1.0f / 16.0f);
        }
        ph[o] = v;
    }

    // folded where-layer1: blocks 0..31, each handles 128 rows
    if (blockIdx.x < 32) {
        int c = threadIdx.x & 127;
        int half = threadIdx.x >> 7;
        int r0 = blockIdx.x * 128 + half * 64;
        float w0 = lW1[c], w1 = lW1[128 + c], bb = lb1[c];
        float s = 0.0f, q = 0.0f;
        for (int r = r0; r < r0 + 64; r++) {
            float2 l = ((const float2*)loc)[r];
            float v = fmaf(l.x, w0, fmaf(l.y, w1, bb));
            g_h1l[(size_t)r * 128 + c] = v;
            s += v;
            q += v * v;
        }
        wrs[threadIdx.x] = s;
        wrq[threadIdx.x] = q;
        __syncthreads();
        if (threadIdx.x < 128) {
            g_p1l_s[blockIdx.x * 128 + threadIdx.x] = wrs[threadIdx.x] + wrs[threadIdx.x + 128];
            g_p1l_q[blockIdx.x * 128 + threadIdx.x] = wrq[threadIdx.x] + wrq[threadIdx.x + 128];
        }
    }
}

// ---------------------------------------------------------------------------
// 2) TF32 tensor-core GEMM body. BM=32, BN-tile=128, KB=16. 256 thr = 8 warps
//    (2 m-rows x 4 n-cols), warp tile m16 x n32, mma m16n8k8.
//    TA: apply relu(fma(a, sA[k], tA[k])) on A load (prev-layer BN+ReLU).
//    Fused bias + per-column sum/sumsq partial epilogue.
// ---------------------------------------------------------------------------
template <bool TA, int K, int N>
__device__ __forceinline__ void gemm_body(const float* __restrict__ A,
                                          const float* __restrict__ Bm,
                                          const float* __restrict__ bias,
                                          const float* __restrict__ sA,
                                          const float* __restrict__ tA,
                                          float* __restrict__ C,
                                          float* __restrict__ ps,
                                          float* __restrict__ pq,
                                          int mb, int nb)
{
    __shared__ __align__(16) unsigned char buf[32 * 132 * 4];  // 16896 B
    unsigned* As = (unsigned*)buf;                 // [32][17] tf32
    unsigned* Bs = (unsigned*)(buf + 32 * 17 * 4); // [16][132] tf32
    float*    Cs = (float*)buf;                    // [32][132] (epilogue)
    __shared__ float rs[256], rq[256];

    int tid = threadIdx.x;
    int lane = tid & 31;
    int wid = tid >> 5;
    int wm = wid >> 2;    // 0..1
    int wn = wid & 3;     // 0..3
    int t4 = lane >> 2;   // 0..7
    int tm4 = lane & 3;   // 0..3
    int m0 = mb * 32;
    int n0 = nb * 128;

    float acc[4][4];
    #pragma unroll
    for (int f = 0; f < 4; f++)
        #pragma unroll
        for (int i = 0; i < 4; i++) acc[f][i] = 0.0f;

    for (int k0 = 0; k0 < K; k0 += 16) {
        // A tile 32x16 -> As[m][k] (stride 17)
        #pragma unroll
        for (int i = 0; i < 2; i++) {
            int idx = tid + i * 256;
            int m = idx >> 4;
            int k = idx & 15;
            float v = A[(size_t)(m0 + m) * K + k0 + k];
            if (TA) v = fmaxf(fmaf(v, sA[k0 + k], tA[k0 + k]), 0.0f);
            As[m * 17 + k] = f2tf(v);
        }
        // B tile 16x128 -> Bs[k][n] (stride 132)
        #pragma unroll
        for (int i = 0; i < 8; i++) {
            int idx = tid + i * 256;
            int k = idx >> 7;
            int n = idx & 127;
            Bs[k * 132 + n] = f2tf(Bm[(size_t)(k0 + k) * N + n0 + n]);
        }
        __syncthreads();

        #pragma unroll
        for (int kk = 0; kk < 16; kk += 8) {
            unsigned a[4];
            int ra = (wm * 16 + t4) * 17 + kk + tm4;
            a[0] = As[ra];
            a[1] = As[ra + 8 * 17];
            a[2] = As[ra + 4];
            a[3] = As[ra + 8 * 17 + 4];
            #pragma unroll
            for (int f = 0; f < 4; f++) {
                unsigned bfr[2];
                int nidx = wn * 32 + f * 8 + t4;
                bfr[0] = Bs[(kk + tm4) * 132 + nidx];
                bfr[1] = Bs[(kk + tm4 + 4) * 132 + nidx];
                mma_tf32(acc[f], a, bfr);
            }
        }
        __syncthreads();
    }

    // write fragments to Cs
    {
        int row = wm * 16 + t4;
        #pragma unroll
        for (int f = 0; f < 4; f++) {
            int cb = wn * 32 + f * 8 + 2 * tm4;
            Cs[row * 132 + cb]           = acc[f][0];
            Cs[row * 132 + cb + 1]       = acc[f][1];
            Cs[(row + 8) * 132 + cb]     = acc[f][2];
            Cs[(row + 8) * 132 + cb + 1] = acc[f][3];
        }
    }
    __syncthreads();

    // bias + store + column stats
    {
        int c = tid & 127;
        int half = tid >> 7;
        float bb = bias[n0 + c];
        float s = 0.0f, q = 0.0f;
        #pragma unroll
        for (int i = 0; i < 16; i++) {
            int r = half * 16 + i;
            float v = Cs[r * 132 + c] + bb;
            C[(size_t)(m0 + r) * N + n0 + c] = v;
            s += v;
            q += v * v;
        }
        rs[tid] = s;
        rq[tid] = q;
    }
    __syncthreads();
    if (tid < 128) {
        ps[mb * N + n0 + tid] = rs[tid] + rs[tid + 128];
        pq[mb * N + n0 + tid] = rq[tid] + rq[tid + 128];
    }
}

// layer-1 what GEMM: phi(4096,784) @ W1(784,128)
__global__ void gemm1_kernel(const float* __restrict__ W1,
                             const float* __restrict__ b1)
{
    gemm_body<false, PHI_DIM, 128>(g_phi, W1, b1, nullptr, nullptr,
                                   g_h1w, g_p1w_s, g_p1w_q, blockIdx.y, 0);
}

// layer-2 GEMMs merged: z=0 what, z=1 where. A gets fused BN+ReLU.
__global__ void gemm2_kernel(const float* __restrict__ wW2, const float* __restrict__ wb2,
                             const float* __restrict__ lW2, const float* __restrict__ lb2)
{
    if (blockIdx.z == 0)
        gemm_body<true, 128, 256>(g_h1w, wW2, wb2, g_s1w, g_t1w,
                                  g_h2w, g_p2w_s, g_p2w_q, blockIdx.y, blockIdx.x);
    else
        gemm_body<true, 128, 256>(g_h1l, lW2, lb2, g_s1l, g_t1l,
                                  g_h2l, g_p2l_s, g_p2l_q, blockIdx.y, blockIdx.x);
}

// ---------------------------------------------------------------------------
// 3) Parallel finalize: one block per column.
// ---------------------------------------------------------------------------
__device__ __forceinline__ void reduce_finalize(float s, float q, int c,
                                                const float* __restrict__ gam,
                                                const float* __restrict__ bet,
                                                float* __restrict__ sc_out,
                                                float* __restrict__ sh_out)
{
    __shared__ float rs[128], rq[128];
    rs[threadIdx.x] = s;
    rq[threadIdx.x] = q;
    __syncthreads();
    #pragma unroll
    for (int off = 64; off >= 32; off >>= 1) {
        if (threadIdx.x < off) {
            rs[threadIdx.x] += rs[threadIdx.x + off];
            rq[threadIdx.x] += rq[threadIdx.x + off];
        }
        __syncthreads();
    }
    if (threadIdx.x < 32) {
        float ss = rs[threadIdx.x];
        float qq = rq[threadIdx.x];
        #pragma unroll
        for (int off = 16; off > 0; off >>= 1) {
            ss += __shfl_down_sync(0xffffffffu, ss, off);
            qq += __shfl_down_sync(0xffffffffu, qq, off);
        }
        if (threadIdx.x == 0) {
            float m = ss * (1.0f / BATCH);
            float var = qq * (1.0f / BATCH) - m * m;
            float r = rsqrtf(var + 1e-5f);
            float sc = r * gam[c];
            sc_out[c] = sc;
            sh_out[c] = bet[c] - m * sc;
        }
    }
}

__global__ void finalize1_kernel(const float* __restrict__ g1w, const float* __restrict__ be1w,
                                 const float* __restrict__ g1l, const float* __restrict__ be1l)
{
    int t = threadIdx.x;
    if (blockIdx.x < 128) {
        int c = blockIdx.x;
        reduce_finalize(g_p1w_s[t * 128 + c], g_p1w_q[t * 128 + c],
                        c, g1w, be1w, g_s1w, g_t1w);
    } else {
        int c = blockIdx.x - 128;
        float s = (t < 32) ? g_p1l_s[t * 128 + c] : 0.0f;
        float q = (t < 32) ? g_p1l_q[t * 128 + c] : 0.0f;
        reduce_finalize(s, q, c, g1l, be1l, g_s1l, g_t1l);
    }
}

__global__ void finalize2_kernel(const float* __restrict__ g2w, const float* __restrict__ be2w,
                                 const float* __restrict__ g2l, const float* __restrict__ be2l)
{
    int t = threadIdx.x;
    if (blockIdx.x < 256) {
        int c = blockIdx.x;
        reduce_finalize(g_p2w_s[t * 256 + c], g_p2w_q[t * 256 + c],
                        c, g2w, be2w, g_s2w, g_t2w);
    } else {
        int c = blockIdx.x - 256;
        reduce_finalize(g_p2l_s[t * 256 + c], g_p2l_q[t * 256 + c],
                        c, g2l, be2l, g_s2l, g_t2l);
    }
}

// ---------------------------------------------------------------------------
// 4) Final: out = relu( BN(h2w) + BN(h2l) )
// ---------------------------------------------------------------------------
__global__ void final_kernel(float* __restrict__ out)
{
    int idx = blockIdx.x * 256 + threadIdx.x;
    int c = idx & 255;
    float vw = fmaf(g_h2w[idx], g_s2w[c], g_t2w[c]);
    float vl = fmaf(g_h2l[idx], g_s2l[c], g_t2l[c]);
    float v = vw + vl;
    out[idx] = v > 0.0f ? v : 0.0f;
}

// ---------------------------------------------------------------------------
extern "C" void kernel_launch(void* const* d_in, const int* in_sizes, int n_in,
                              void* d_out, int out_size)
{
    const float* x    = (const float*)d_in[0];
    const float* loc  = (const float*)d_in[1];
    const float* wW1  = (const float*)d_in[2];
    const float* wb1  = (const float*)d_in[3];
    const float* wg1  = (const float*)d_in[4];
    const float* wbe1 = (const float*)d_in[5];
    const float* wW2  = (const float*)d_in[6];
    const float* wb2  = (const float*)d_in[7];
    const float* wg2  = (const float*)d_in[8];
    const float* wbe2 = (const float*)d_in[9];
    const float* lW1  = (const float*)d_in[10];
    const float* lb1  = (const float*)d_in[11];
    const float* lg1  = (const float*)d_in[12];
    const float* lbe1 = (const float*)d_in[13];
    const float* lW2  = (const float*)d_in[14];
    const float* lb2  = (const float*)d_in[15];
    const float* lg2  = (const float*)d_in[16];
    const float* lbe2 = (const float*)d_in[17];
    float* out = (float*)d_out;

    float* phi;
    cudaGetSymbolAddress((void**)&phi, g_phi);

    // 1) foveate -> phi, + folded where-layer1 (blocks 0..31)
    foveate_kernel<<<BATCH, 256>>>(x, loc, phi, lW1, lb1);

    // 2) what layer1 (tf32 MMA, fused stats partials)
    {
        dim3 grid(1, BATCH / 32);
        gemm1_kernel<<<grid, 256>>>(wW1, wb1);
    }

    // 3) finalize layer-1 BN params (parallel)
    finalize1_kernel<<<256, 128>>>(wg1, wbe1, lg1, lbe1);

    // 4) both layer-2 GEMMs (tf32 MMA, fused BN+ReLU on A, stats partials)
    {
        dim3 grid(2, BATCH / 32, 2);
        gemm2_kernel<<<grid, 256>>>(wW2, wb2, lW2, lb2);
    }

    // 5) finalize layer-2 BN params (parallel)
    finalize2_kernel<<<512, 128>>>(wg2, wbe2, lg2, lbe2);

    // 6) final add + relu
    final_kernel<<<BATCH * 256 / 256, 256>>>(out);
}

// round 5
// speedup vs baseline: 2.3432x; 1.2498x over previous
#include <cuda_runtime.h>

// ---------------------------------------------------------------------------
// GlimpseNetwork fused pipeline.  B=4096, H=128, G=14, patches 14/28/56/112.
// TF32 tensor-core GEMMs (fragment-major SMEM, pipelined), fused BN stats.
// ---------------------------------------------------------------------------

#define BATCH 4096
#define HIMG  128
#define PHI_DIM 784

// Scratch (device globals; no cudaMalloc allowed)
__device__ __align__(16) float g_phi[BATCH * PHI_DIM];
__device__ __align__(16) float g_h1w[BATCH * 128];
__device__ __align__(16) float g_h1l[BATCH * 128];
__device__ __align__(16) float g_h2w[BATCH * 256];
__device__ __align__(16) float g_h2l[BATCH * 256];
// tf32 fragment-major weights (filled by foveate's spare blocks)
__device__ __align__(16) float g_W1f[PHI_DIM * 128];
__device__ __align__(16) float g_W2wf[128 * 256];
__device__ __align__(16) float g_W2lf[128 * 256];
// per-block column partials (deterministic: no atomics)
__device__ float g_p1w_s[128 * 128], g_p1w_q[128 * 128];
__device__ float g_p1l_s[32 * 128],  g_p1l_q[32 * 128];
__device__ float g_p2w_s[64 * 256],  g_p2w_q[64 * 256];
__device__ float g_p2l_s[64 * 256],  g_p2l_q[64 * 256];
// fused BN transforms: h_norm = fma(h, scale, shift)
__device__ float g_s1w[128], g_t1w[128], g_s1l[128], g_t1l[128];
__device__ float g_s2w[256], g_t2w[256], g_s2l[256], g_t2l[256];

__device__ __forceinline__ unsigned f2tf(float v) {
    unsigned r;
    asm("cvt.rna.tf32.f32 %0, %1;" : "=r"(r) : "f"(v));
    return r;
}

__device__ __forceinline__ void mma_tf32(float* d, const unsigned* a, const unsigned* b) {
    asm volatile(
        "mma.sync.aligned.m16n8k8.row.col.f32.tf32.tf32.f32 "
        "{%0,%1,%2,%3}, {%4,%5,%6,%7}, {%8,%9}, {%0,%1,%2,%3};"
        : "+f"(d[0]), "+f"(d[1]), "+f"(d[2]), "+f"(d[3])
        : "r"(a[0]), "r"(a[1]), "r"(a[2]), "r"(a[3]), "r"(b[0]), "r"(b[1]));
}

// ---------------------------------------------------------------------------
// Weight -> tf32 fragment-major conversion.
// Layout: [k16-chunk][ (k8)*(Nw/16)+n16 ][ lane*4 + half*2 + slot ]
//   lane=(n%8)*4+(k%4), half=(n%16)/8, slot=(k%8)/4
// ---------------------------------------------------------------------------
__device__ __forceinline__ void conv_frag(const float* __restrict__ W,
                                          float* __restrict__ Wf,
                                          int Kw, int Nw, int tid0, int nthreads)
{
    int total = Kw * Nw;
    for (int e = tid0; e < total; e += nthreads) {
        int kk = e / Nw, n = e - kk * Nw;
        int pos = (kk >> 4) * (Nw * 16)
                + (((kk >> 3) & 1) * (Nw >> 4) + (n >> 4)) * 128
                + (((n & 7) << 2) + (kk & 3)) * 4
                + (((n >> 3) & 1) << 1) + ((kk >> 2) & 1);
        Wf[pos] = __uint_as_float(f2tf(W[e]));
    }
}

// ---------------------------------------------------------------------------
// 1) Foveate (2x2-pooled pyramid) + folded where-layer1 (blocks 0..31)
//    + folded weight conversions (blocks 32..95).
// ---------------------------------------------------------------------------
__global__ void foveate_kernel(const float* __restrict__ x,
                               const float* __restrict__ loc,
                               float* __restrict__ phi,
                               const float* __restrict__ lW1,
                               const float* __restrict__ lb1,
                               const float* __restrict__ wW1,
                               const float* __restrict__ wW2,
                               const float* __restrict__ lW2)
{
    __shared__ float pooled[56 * 57];
    __shared__ float center[196];
    __shared__ float wrs[256], wrq[256];
    int b = blockIdx.x;
    float lx = loc[2 * b + 0];
    float ly = loc[2 * b + 1];
    int cx = (int)(0.5f * ((lx + 1.0f) * 128.0f));
    int cy = (int)(0.5f * ((ly + 1.0f) * 128.0f));
    int row0 = cy - 56;
    int col0 = cx - 56;
    const float* __restrict__ img = x + (size_t)b * HIMG * HIMG;

    for (int idx = threadIdx.x; idx < 56 * 56; idx += 256) {
        int pr = idx / 56;
        int pc = idx - pr * 56;
        int r = row0 + 2 * pr;
        int c = col0 + 2 * pc;
        float s = 0.0f;
        bool r0ok = (unsigned)r < 128u, r1ok = (unsigned)(r + 1) < 128u;
        bool c0ok = (unsigned)c < 128u, c1ok = (unsigned)(c + 1) < 128u;
        if (r0ok && c0ok) s += img[r * HIMG + c];
        if (r0ok && c1ok) s += img[r * HIMG + c + 1];
        if (r1ok && c0ok) s += img[(r + 1) * HIMG + c];
        if (r1ok && c1ok) s += img[(r + 1) * HIMG + c + 1];
        pooled[pr * 57 + pc] = s * 0.25f;
    }
    if (threadIdx.x < 196) {
        int i = threadIdx.x / 14;
        int j = threadIdx.x - i * 14;
        int r = row0 + 49 + i;
        int c = col0 + 49 + j;
        float v = 0.0f;
        if ((unsigned)r < 128u && (unsigned)c < 128u) v = img[r * HIMG + c];
        center[threadIdx.x] = v;
    }
    __syncthreads();

    float* __restrict__ ph = phi + (size_t)b * PHI_DIM;
    for (int o = threadIdx.x; o < PHI_DIM; o += 256) {
        int p = o / 196;
        int rem = o - p * 196;
        int i = rem / 14;
        int j = rem - i * 14;
        float v;
        if (p == 0) {
            v = center[rem];
        } else if (p == 1) {
            v = pooled[(21 + i) * 57 + 21 + j];
        } else if (p == 2) {
            int base = (14 + 2 * i) * 57 + 14 + 2 * j;
            v = (pooled[base] + pooled[base + 1] +
                 pooled[base + 57] + pooled[base + 58]) * 0.25f;
        } else {
            int base = (4 * i) * 57 + 4 * j;
            float s = 0.0f;
            #pragma unroll
            for (int di = 0; di < 4; di++)
                #pragma unroll
                for (int dj = 0; dj < 4; dj++)
                    s += pooled[base + di * 57 + dj];
            v = s * (1.0f / 16.0f);
        }
        ph[o] = v;
    }

    // folded where-layer1: blocks 0..31
    if (blockIdx.x < 32) {
        int c = threadIdx.x & 127;
        int half = threadIdx.x >> 7;
        int r0 = blockIdx.x * 128 + half * 64;
        float w0 = lW1[c], w1 = lW1[128 + c], bb = lb1[c];
        float s = 0.0f, q = 0.0f;
        for (int r = r0; r < r0 + 64; r++) {
            float2 l = ((const float2*)loc)[r];
            float v = fmaf(l.x, w0, fmaf(l.y, w1, bb));
            g_h1l[(size_t)r * 128 + c] = v;
            s += v;
            q += v * v;
        }
        wrs[threadIdx.x] = s;
        wrq[threadIdx.x] = q;
        __syncthreads();
        if (threadIdx.x < 128) {
            g_p1l_s[blockIdx.x * 128 + threadIdx.x] = wrs[threadIdx.x] + wrs[threadIdx.x + 128];
            g_p1l_q[blockIdx.x * 128 + threadIdx.x] = wrq[threadIdx.x] + wrq[threadIdx.x + 128];
        }
    } else if (blockIdx.x < 80) {          // W1 conversion: 48 blocks
        conv_frag(wW1, g_W1f, PHI_DIM, 128,
                  (blockIdx.x - 32) * 256 + threadIdx.x, 48 * 256);
    } else if (blockIdx.x < 88) {          // W2 what: 8 blocks
        conv_frag(wW2, g_W2wf, 128, 256,
                  (blockIdx.x - 80) * 256 + threadIdx.x, 8 * 256);
    } else if (blockIdx.x < 96) {          // W2 where: 8 blocks
        conv_frag(lW2, g_W2lf, 128, 256,
                  (blockIdx.x - 88) * 256 + threadIdx.x, 8 * 256);
    }
}

// ---------------------------------------------------------------------------
// 2) Pipelined tf32 MMA GEMM. 256 thr = 8 warps (2 m-warps x 4 n-warps).
//    Warp tile: (WM*16) x (WN*8).  Fragment-major SMEM, 2-stage pipeline.
//    B comes pre-converted (fragment-major tf32) from gmem.
//    TA: apply relu(fma(a, sA[k], tA[k])) on A load.
// ---------------------------------------------------------------------------
template <bool TA, int K, int N, int BM, int BN, int WM, int WN>
__device__ __forceinline__ void gemm_body(const float* __restrict__ A,
                                          const float4* __restrict__ Bf,
                                          const float* __restrict__ bias,
                                          const float* __restrict__ sA,
                                          const float* __restrict__ tA,
                                          float* __restrict__ C,
                                          float* __restrict__ ps,
                                          float* __restrict__ pq,
                                          int mb, int nb)
{
    constexpr int NB16 = BN / 16;
    constexpr int STAGE_A = BM * 16;       // floats per stage
    constexpr int STAGE_B = BN * 16;
    constexpr int STAGE = STAGE_A + STAGE_B;
    constexpr int CSS = BN + 4;
    constexpr int BUFSZ = (2 * STAGE > BM * CSS) ? 2 * STAGE : BM * CSS;
    constexpr int STEPS = K / 16;
    constexpr int SK = TA ? K : 1;

    __shared__ __align__(16) float buf[BUFSZ];
    __shared__ float rs[256], rq[256];
    __shared__ float sSc[SK], sSh[SK];

    int tid = threadIdx.x;
    int lane = tid & 31;
    int wid = tid >> 5;
    int wn = wid & 3;
    int wm = wid >> 2;
    int m0 = mb * BM;
    int n0 = nb * BN;

    if (TA) {
        if (tid < K) { sSc[tid] = sA[tid]; sSh[tid] = tA[tid]; }
    }
    __syncthreads();

    float4 aReg;
    float4 bReg[BN / 64];

    auto ldA = [&](int step) {
        if (tid < BM * 4) {
            int m = tid >> 2, kq = tid & 3;
            aReg = *(const float4*)&A[(size_t)(m0 + m) * K + step * 16 + kq * 4];
        }
    };
    auto ldB = [&](int step) {
        const float4* src = Bf + (size_t)step * (N * 4);
        #pragma unroll
        for (int e = 0; e < BN / 64; e++) {
            int u = tid + e * 256;
            int k8 = u / (NB16 * 32);
            int rem = u - k8 * (NB16 * 32);
            bReg[e] = src[k8 * (N / 16) * 32 + (n0 / 16) * 32 + rem];
        }
    };
    auto stA = [&](float* As, int step) {
        if (tid < BM * 4) {
            int m = tid >> 2, kq = tid & 3;
            float v4[4] = {aReg.x, aReg.y, aReg.z, aReg.w};
            #pragma unroll
            for (int j = 0; j < 4; j++) {
                int k = kq * 4 + j;
                float v = v4[j];
                if (TA) v = fmaxf(fmaf(v, sSc[step * 16 + k], sSh[step * 16 + k]), 0.0f);
                int frag = (k >> 3) * (BM / 16) + (m >> 4);
                int pos = frag * 128 + (((m & 7) << 2) + (k & 3)) * 4
                        + ((m >> 3) & 1) + (((k >> 2) & 1) << 1);
                ((unsigned*)As)[pos] = f2tf(v);
            }
        }
    };
    auto stB = [&](float* Bs) {
        #pragma unroll
        for (int e = 0; e < BN / 64; e++)
            ((float4*)Bs)[tid + e * 256] = bReg[e];
    };

    float acc[WM][WN][4];
    #pragma unroll
    for (int i = 0; i < WM; i++)
        #pragma unroll
        for (int f = 0; f < WN; f++)
            #pragma unroll
            for (int v = 0; v < 4; v++) acc[i][f][v] = 0.0f;

    auto compute = [&](const float* As, const float* Bs) {
        #pragma unroll
        for (int k8 = 0; k8 < 2; k8++) {
            unsigned a[WM][4];
            #pragma unroll
            for (int i = 0; i < WM; i++)
                *(uint4*)a[i] = *(const uint4*)&((const unsigned*)As)[
                    (k8 * (BM / 16) + wm * WM + i) * 128 + lane * 4];
            #pragma unroll
            for (int j = 0; j < WN / 2; j++) {
                uint4 bb = *(const uint4*)&((const unsigned*)Bs)[
                    (k8 * NB16 + wn * (WN / 2) + j) * 128 + lane * 4];
                unsigned bl[2] = {bb.x, bb.y};
                unsigned bh[2] = {bb.z, bb.w};
                #pragma unroll
                for (int i = 0; i < WM; i++) {
                    mma_tf32(acc[i][2 * j],     a[i], bl);
                    mma_tf32(acc[i][2 * j + 1], a[i], bh);
                }
            }
        }
    };

    // pipeline prologue
    ldA(0); ldB(0);
    stA(buf, 0); stB(buf + STAGE_A);
    if (STEPS > 1) { ldA(1); ldB(1); }
    __syncthreads();

    for (int s = 0; s < STEPS; s++) {
        int cur = s & 1, nxt = cur ^ 1;
        float* curBuf = buf + cur * STAGE;
        if (s + 1 < STEPS) {
            float* nxtBuf = buf + nxt * STAGE;
            stA(nxtBuf, s + 1);
            stB(nxtBuf + STAGE_A);
        }
        if (s + 2 < STEPS) { ldA(s + 2); ldB(s + 2); }
        compute(curBuf, curBuf + STAGE_A);
        __syncthreads();
    }

    // epilogue: fragments -> Cs (overlays stage buffers; all compute done)
    float* Cs = buf;
    #pragma unroll
    for (int i = 0; i < WM; i++) {
        int row = (wm * WM + i) * 16 + (lane >> 2);
        #pragma unroll
        for (int f = 0; f < WN; f++) {
            int cb = wn * WN * 8 + f * 8 + 2 * (lane & 3);
            *(float2*)&Cs[row * CSS + cb]       = make_float2(acc[i][f][0], acc[i][f][1]);
            *(float2*)&Cs[(row + 8) * CSS + cb] = make_float2(acc[i][f][2], acc[i][f][3]);
        }
    }
    __syncthreads();

    // bias + store + column stats
    {
        constexpr int RPT = BM * BN / 256;   // rows per thread
        int c = tid & (BN - 1);
        int h = tid / BN;
        float bb = bias[n0 + c];
        float s = 0.0f, q = 0.0f;
        #pragma unroll
        for (int i = 0; i < RPT; i++) {
            int r = h * RPT + i;
            float v = Cs[r * CSS + c] + bb;
            C[(size_t)(m0 + r) * N + n0 + c] = v;
            s += v;
            q += v * v;
        }
        rs[tid] = s;
        rq[tid] = q;
    }
    __syncthreads();
    if (tid < BN) {
        float s = 0.0f, q = 0.0f;
        #pragma unroll
        for (int g = 0; g < 256 / BN; g++) { s += rs[g * BN + tid]; q += rq[g * BN + tid]; }
        ps[mb * N + n0 + tid] = s;
        pq[mb * N + n0 + tid] = q;
    }
}

// layer-1 what GEMM: phi(4096,784) @ W1(784,128).  BM=32 BN=64, grid (2,128).
__global__ void __launch_bounds__(256) gemm1_kernel(const float* __restrict__ b1)
{
    gemm_body<false, PHI_DIM, 128, 32, 64, 1, 2>(
        g_phi, (const float4*)g_W1f, b1, nullptr, nullptr,
        g_h1w, g_p1w_s, g_p1w_q, blockIdx.y, blockIdx.x);
}

// layer-2 GEMMs merged: z=0 what, z=1 where.  BM=64 BN=128, grid (2,64,2).
__global__ void __launch_bounds__(256) gemm2_kernel(const float* __restrict__ wb2,
                                                    const float* __restrict__ lb2)
{
    if (blockIdx.z == 0)
        gemm_body<true, 128, 256, 64, 128, 2, 4>(
            g_h1w, (const float4*)g_W2wf, wb2, g_s1w, g_t1w,
            g_h2w, g_p2w_s, g_p2w_q, blockIdx.y, blockIdx.x);
    else
        gemm_body<true, 128, 256, 64, 128, 2, 4>(
            g_h1l, (const float4*)g_W2lf, lb2, g_s1l, g_t1l,
            g_h2l, g_p2l_s, g_p2l_q, blockIdx.y, blockIdx.x);
}

// ---------------------------------------------------------------------------
// 3) Parallel finalize: one block per column.
// ---------------------------------------------------------------------------
__device__ __forceinline__ void reduce_finalize(float s, float q, int c,
                                                const float* __restrict__ gam,
                                                const float* __restrict__ bet,
                                                float* __restrict__ sc_out,
                                                float* __restrict__ sh_out)
{
    __shared__ float rs[128], rq[128];
    rs[threadIdx.x] = s;
    rq[threadIdx.x] = q;
    __syncthreads();
    #pragma unroll
    for (int off = 64; off >= 32; off >>= 1) {
        if (threadIdx.x < off) {
            rs[threadIdx.x] += rs[threadIdx.x + off];
            rq[threadIdx.x] += rq[threadIdx.x + off];
        }
        __syncthreads();
    }
    if (threadIdx.x < 32) {
        float ss = rs[threadIdx.x];
        float qq = rq[threadIdx.x];
        #pragma unroll
        for (int off = 16; off > 0; off >>= 1) {
            ss += __shfl_down_sync(0xffffffffu, ss, off);
            qq += __shfl_down_sync(0xffffffffu, qq, off);
        }
        if (threadIdx.x == 0) {
            float m = ss * (1.0f / BATCH);
            float var = qq * (1.0f / BATCH) - m * m;
            float r = rsqrtf(var + 1e-5f);
            float sc = r * gam[c];
            sc_out[c] = sc;
            sh_out[c] = bet[c] - m * sc;
        }
    }
}

__global__ void finalize1_kernel(const float* __restrict__ g1w, const float* __restrict__ be1w,
                                 const float* __restrict__ g1l, const float* __restrict__ be1l)
{
    int t = threadIdx.x;
    if (blockIdx.x < 128) {
        int c = blockIdx.x;
        reduce_finalize(g_p1w_s[t * 128 + c], g_p1w_q[t * 128 + c],
                        c, g1w, be1w, g_s1w, g_t1w);
    } else {
        int c = blockIdx.x - 128;
        float s = (t < 32) ? g_p1l_s[t * 128 + c] : 0.0f;
        float q = (t < 32) ? g_p1l_q[t * 128 + c] : 0.0f;
        reduce_finalize(s, q, c, g1l, be1l, g_s1l, g_t1l);
    }
}

__global__ void finalize2_kernel(const float* __restrict__ g2w, const float* __restrict__ be2w,
                                 const float* __restrict__ g2l, const float* __restrict__ be2l)
{
    int t = threadIdx.x;
    if (blockIdx.x < 256) {
        int c = blockIdx.x;
        float s = (t < 64) ? g_p2w_s[t * 256 + c] : 0.0f;
        float q = (t < 64) ? g_p2w_q[t * 256 + c] : 0.0f;
        reduce_finalize(s, q, c, g2w, be2w, g_s2w, g_t2w);
    } else {
        int c = blockIdx.x - 256;
        float s = (t < 64) ? g_p2l_s[t * 256 + c] : 0.0f;
        float q = (t < 64) ? g_p2l_q[t * 256 + c] : 0.0f;
        reduce_finalize(s, q, c, g2l, be2l, g_s2l, g_t2l);
    }
}

// ---------------------------------------------------------------------------
// 4) Final: out = relu( BN(h2w) + BN(h2l) )
// ---------------------------------------------------------------------------
__global__ void final_kernel(float* __restrict__ out)
{
    int idx = blockIdx.x * 256 + threadIdx.x;
    int c = idx & 255;
    float vw = fmaf(g_h2w[idx], g_s2w[c], g_t2w[c]);
    float vl = fmaf(g_h2l[idx], g_s2l[c], g_t2l[c]);
    float v = vw + vl;
    out[idx] = v > 0.0f ? v : 0.0f;
}

// ---------------------------------------------------------------------------
extern "C" void kernel_launch(void* const* d_in, const int* in_sizes, int n_in,
                              void* d_out, int out_size)
{
    const float* x    = (const float*)d_in[0];
    const float* loc  = (const float*)d_in[1];
    const float* wW1  = (const float*)d_in[2];
    const float* wb1  = (const float*)d_in[3];
    const float* wg1  = (const float*)d_in[4];
    const float* wbe1 = (const float*)d_in[5];
    const float* wW2  = (const float*)d_in[6];
    const float* wb2  = (const float*)d_in[7];
    const float* wg2  = (const float*)d_in[8];
    const float* wbe2 = (const float*)d_in[9];
    const float* lW1  = (const float*)d_in[10];
    const float* lb1  = (const float*)d_in[11];
    const float* lg1  = (const float*)d_in[12];
    const float* lbe1 = (const float*)d_in[13];
    const float* lW2  = (const float*)d_in[14];
    const float* lb2  = (const float*)d_in[15];
    const float* lg2  = (const float*)d_in[16];
    const float* lbe2 = (const float*)d_in[17];
    float* out = (float*)d_out;

    float* phi;
    cudaGetSymbolAddress((void**)&phi, g_phi);

    // 1) foveate -> phi, + where-layer1 (blk 0..31) + weight conv (blk 32..95)
    foveate_kernel<<<BATCH, 256>>>(x, loc, phi, lW1, lb1, wW1, wW2, lW2);

    // 2) what layer1 (pipelined tf32 MMA, fused stats partials)
    {
        dim3 grid(2, BATCH / 32);
        gemm1_kernel<<<grid, 256>>>(wb1);
    }

    // 3) finalize layer-1 BN params
    finalize1_kernel<<<256, 128>>>(wg1, wbe1, lg1, lbe1);

    // 4) both layer-2 GEMMs (fused BN+ReLU on A, stats partials)
    {
        dim3 grid(2, BATCH / 64, 2);
        gemm2_kernel<<<grid, 256>>>(wb2, lb2);
    }

    // 5) finalize layer-2 BN params
    finalize2_kernel<<<512, 128>>>(wg2, wbe2, lg2, lbe2);

    // 6) final add + relu
    final_kernel<<<BATCH * 256 / 256, 256>>>(out);
}